// round 16
// baseline (speedup 1.0000x reference)
#include <cuda_runtime.h>
#include <cuda_fp16.h>
#include <stdint.h>

#define B_USERS     4096
#define D_DIM       64
#define NNZ_CNT     204800
#define N_PAIRS     1048576
#define NUM_ITEMS_C 100000
#define MAX_PER_ROW 128

#define PRE_BLOCKS   (NUM_ITEMS_C * D_DIM / 8 / 256) // 3125 (800000 threads exact)
#define BIN_BLOCKS   (NNZ_CNT / 256)                 // 800
#define ROW_BLOCKS   (B_USERS / 8)                   // 512 (8 warps/blk, 1 warp/row)

#define DECODE_BLOCKS (N_PAIRS * 2 / 256)            // 8192
#define ITEM_SEG      100352
#define USER_SEG      (B_USERS * 16)                 // 65536
#define TAIL_THREADS  (ITEM_SEG + USER_SEG)          // 165888
#define TAIL_BLOCKS   (TAIL_THREADS / 256)           // 648

// Scratch (no cudaMalloc allowed).
// INVARIANTS at every kernel_launch entry (static zero-init; k_row re-zeros
// g_cnt, decode's reg tail re-zeros g_mask):  g_cnt == 0, g_mask == 0.
__device__ __half        g_hidden_h[B_USERS * D_DIM];
__device__ __half        g_de_h[NUM_ITEMS_C * D_DIM];
__device__ float         g_item_reg[NUM_ITEMS_C];
__device__ unsigned char g_mask[NUM_ITEMS_C];
__device__ int           g_cnt[B_USERS];
__device__ int           g_items[B_USERS * MAX_PER_ROW];

// ---------------- Threefry-2x32 (JAX partitionable path) ----------------
__device__ __forceinline__ uint32_t rotl32(uint32_t x, int r) {
    return (x << r) | (x >> (32 - r));
}

__device__ __forceinline__ uint32_t threefry_bits(uint32_t ctr_lo) {
    const uint32_t ks0 = 0u, ks1 = 42u;
    const uint32_t ks2 = ks0 ^ ks1 ^ 0x1BD11BDAu;
    uint32_t x0 = 0u  + ks0;
    uint32_t x1 = ctr_lo + ks1;

    x0 += x1; x1 = rotl32(x1, 13); x1 ^= x0;
    x0 += x1; x1 = rotl32(x1, 15); x1 ^= x0;
    x0 += x1; x1 = rotl32(x1, 26); x1 ^= x0;
    x0 += x1; x1 = rotl32(x1,  6); x1 ^= x0;
    x0 += ks1; x1 += ks2 + 1u;
    x0 += x1; x1 = rotl32(x1, 17); x1 ^= x0;
    x0 += x1; x1 = rotl32(x1, 29); x1 ^= x0;
    x0 += x1; x1 = rotl32(x1, 16); x1 ^= x0;
    x0 += x1; x1 = rotl32(x1, 24); x1 ^= x0;
    x0 += ks2; x1 += ks0 + 2u;
    x0 += x1; x1 = rotl32(x1, 13); x1 ^= x0;
    x0 += x1; x1 = rotl32(x1, 15); x1 ^= x0;
    x0 += x1; x1 = rotl32(x1, 26); x1 ^= x0;
    x0 += x1; x1 = rotl32(x1,  6); x1 ^= x0;
    x0 += ks0; x1 += ks1 + 3u;
    x0 += x1; x1 = rotl32(x1, 17); x1 ^= x0;
    x0 += x1; x1 = rotl32(x1, 29); x1 ^= x0;
    x0 += x1; x1 = rotl32(x1, 16); x1 ^= x0;
    x0 += x1; x1 = rotl32(x1, 24); x1 ^= x0;
    x0 += ks1; x1 += ks2 + 4u;
    x0 += x1; x1 = rotl32(x1, 13); x1 ^= x0;
    x0 += x1; x1 = rotl32(x1, 15); x1 ^= x0;
    x0 += x1; x1 = rotl32(x1, 26); x1 ^= x0;
    x0 += x1; x1 = rotl32(x1,  6); x1 ^= x0;
    x0 += ks2; x1 += ks0 + 5u;

    return x0 ^ x1;
}

// ---------------- fp16 pack helpers ----------------
__device__ __forceinline__ uint32_t pack_h2(float a, float b) {
    __half2 h = __floats2half2_rn(a, b);
    return *reinterpret_cast<uint32_t*>(&h);
}
__device__ __forceinline__ uint4 pack_8(float4 a, float4 b) {
    return make_uint4(pack_h2(a.x, a.y), pack_h2(a.z, a.w),
                      pack_h2(b.x, b.y), pack_h2(b.z, b.w));
}
__device__ __forceinline__ float sumsq4(float4 v) {
    return v.x * v.x + v.y * v.y + v.z * v.z + v.w * v.w;
}

// ---------------- K1: pre (normal launch) — R8-exact streaming layout ----------------
__global__ void __launch_bounds__(256) k_pre(
        const float* __restrict__ de_emb,
        const float* __restrict__ en_emb,
        const float* __restrict__ de_bias,
        float* reg_out) {
    int idx = blockIdx.x * blockDim.x + threadIdx.x;   // 0..799999 exact
    int row = idx >> 3;
    int l8  = idx & 7;

    float4 a  = __ldg((const float4*)de_emb + idx * 2);
    float4 b  = __ldg((const float4*)de_emb + idx * 2 + 1);
    float4 ea = __ldg((const float4*)en_emb + idx * 2);
    float4 eb = __ldg((const float4*)en_emb + idx * 2 + 1);

    ((uint4*)g_de_h)[idx] = pack_8(a, b);

    float c = sumsq4(a) + sumsq4(b) + sumsq4(ea) + sumsq4(eb);
    c += __shfl_xor_sync(0xffffffffu, c, 1);
    c += __shfl_xor_sync(0xffffffffu, c, 2);
    c += __shfl_xor_sync(0xffffffffu, c, 4);
    if (l8 == 0) {
        float bb = __ldg(de_bias + row);
        g_item_reg[row] = c + bb * bb;
    }
    if (idx == 0 && reg_out) *reg_out = 0.0f;
}

// ---------------- K2: bin + item-mask (PDL, NO sync -> overlaps k_pre) ----------------
// Touches only g_cnt/g_items/g_mask (zero by invariant) and pure inputs.
__global__ void __launch_bounds__(256) k_bin(
        const int* __restrict__ sp_row,
        const int* __restrict__ sp_col,
        const int* __restrict__ bat_items) {
    int t = blockIdx.x * blockDim.x + threadIdx.x;   // 0..NNZ-1 exact

    uint32_t bits = threefry_bits((uint32_t)t);
    float u = __uint_as_float((bits >> 9) | 0x3f800000u) - 1.0f;
    if (u < 0.8f) {
        int row = __ldg(sp_row + t);
        int pos = atomicAdd(&g_cnt[row], 1);
        if (pos < MAX_PER_ROW)
            g_items[row * MAX_PER_ROW + pos] = __ldg(sp_col + t);
    }
    // grid-stride item mask (N_PAIRS / NNZ = 5.12 iters/thread)
    for (int m = t; m < N_PAIRS; m += NNZ_CNT)
        g_mask[__ldg(bat_items + m)] = 1;
}

// ---------------- K3: per-row gather-sum + tanh + fp16 (PDL + sync) ----------------
__global__ void __launch_bounds__(256) k_row(
        const int*   __restrict__ user_ids,
        const float* __restrict__ user_emb,
        const float* __restrict__ en_offset,
        const float* __restrict__ en_emb) {
    int w    = (blockIdx.x * blockDim.x + threadIdx.x) >> 5;   // row 0..4095
    int lane = threadIdx.x & 31;

    int uid = __ldg(user_ids + w);
    float2 u = __ldg((const float2*)user_emb + (size_t)uid * 32 + lane);
    float2 o = __ldg((const float2*)en_offset + lane);

    cudaGridDependencySynchronize();   // bin lists complete

    int n = g_cnt[w];
    if (n > MAX_PER_ROW) n = MAX_PER_ROW;
    const int* lst = g_items + w * MAX_PER_ROW;

    float2 acc = make_float2(0.0f, 0.0f);
    int j = 0;
    for (; j + 4 <= n; j += 4) {
        int c0 = __ldg(lst + j), c1 = __ldg(lst + j + 1);
        int c2 = __ldg(lst + j + 2), c3 = __ldg(lst + j + 3);
        float2 v0 = __ldg((const float2*)en_emb + (size_t)c0 * 32 + lane);
        float2 v1 = __ldg((const float2*)en_emb + (size_t)c1 * 32 + lane);
        float2 v2 = __ldg((const float2*)en_emb + (size_t)c2 * 32 + lane);
        float2 v3 = __ldg((const float2*)en_emb + (size_t)c3 * 32 + lane);
        acc.x += (v0.x + v1.x) + (v2.x + v3.x);
        acc.y += (v0.y + v1.y) + (v2.y + v3.y);
    }
    for (; j < n; j++) {
        int c = __ldg(lst + j);
        float2 v = __ldg((const float2*)en_emb + (size_t)c * 32 + lane);
        acc.x += v.x; acc.y += v.y;
    }

    float hx = tanhf(1.25f * acc.x + u.x + o.x);
    float hy = tanhf(1.25f * acc.y + u.y + o.y);
    ((uint32_t*)g_hidden_h)[w * 32 + lane] = pack_h2(hx, hy);

    if (lane == 0) g_cnt[w] = 0;   // restore invariant
}

// ---------------- K4: decode + reg tail (PDL + sync; re-zeros g_mask) ----------------
__device__ __forceinline__ float dot8h(uint4 hv, uint4 ev) {
    float acc = 0.0f;
    const uint32_t* hw = (const uint32_t*)&hv;
    const uint32_t* ew = (const uint32_t*)&ev;
#pragma unroll
    for (int i = 0; i < 4; i++) {
        float2 f = __half22float2(*(const __half2*)&hw[i]);
        float2 g = __half22float2(*(const __half2*)&ew[i]);
        acc += f.x * g.x + f.y * g.y;
    }
    return acc;
}

__global__ void __launch_bounds__(256) k_decode_reg(
        const int* __restrict__ bat_idx,
        const int* __restrict__ bat_items,
        const float* __restrict__ de_bias,
        const float* __restrict__ en_offset,
        const float* __restrict__ user_emb,
        const int*   __restrict__ user_ids,
        float* __restrict__ out,
        float* __restrict__ reg_out) {
    if (blockIdx.x < DECODE_BLOCKS) {
        int t = blockIdx.x * blockDim.x + threadIdx.x;
        int g = t >> 3;             // group handles pairs 4g..4g+3
        int l = t & 7;

        int4 bb = __ldg((const int4*)bat_idx + g);
        int4 ii = __ldg((const int4*)bat_items + g);
        cudaGridDependencySynchronize();   // hidden_h (K3), de_h (K1)

        uint4 h0 = ((const uint4*)g_hidden_h + (size_t)bb.x * 8)[l];
        uint4 h1 = ((const uint4*)g_hidden_h + (size_t)bb.y * 8)[l];
        uint4 h2 = ((const uint4*)g_hidden_h + (size_t)bb.z * 8)[l];
        uint4 h3 = ((const uint4*)g_hidden_h + (size_t)bb.w * 8)[l];
        uint4 e0 = ((const uint4*)g_de_h + (size_t)ii.x * 8)[l];
        uint4 e1 = ((const uint4*)g_de_h + (size_t)ii.y * 8)[l];
        uint4 e2 = ((const uint4*)g_de_h + (size_t)ii.z * 8)[l];
        uint4 e3 = ((const uint4*)g_de_h + (size_t)ii.w * 8)[l];

        float p0 = dot8h(h0, e0);
        float p1 = dot8h(h1, e1);
        float p2 = dot8h(h2, e2);
        float p3 = dot8h(h3, e3);
#pragma unroll
        for (int s = 1; s <= 4; s <<= 1) {
            p0 += __shfl_xor_sync(0xffffffffu, p0, s);
            p1 += __shfl_xor_sync(0xffffffffu, p1, s);
            p2 += __shfl_xor_sync(0xffffffffu, p2, s);
            p3 += __shfl_xor_sync(0xffffffffu, p3, s);
        }
        if (l == 0) {
            float4 r = make_float4(p0 + __ldg(de_bias + ii.x),
                                   p1 + __ldg(de_bias + ii.y),
                                   p2 + __ldg(de_bias + ii.z),
                                   p3 + __ldg(de_bias + ii.w));
            ((float4*)out)[g] = r;
        }
    } else {
        cudaGridDependencySynchronize();
        __shared__ float bacc;
        if (threadIdx.x == 0) bacc = 0.0f;
        __syncthreads();

        int t = (blockIdx.x - DECODE_BLOCKS) * blockDim.x + threadIdx.x;
        float c = 0.0f;
        if (t < NUM_ITEMS_C) {
            c = g_mask[t] ? g_item_reg[t] : 0.0f;
            g_mask[t] = 0;   // restore invariant
            if (t == 0) {
                for (int k = 0; k < D_DIM; k++) {
                    float o = __ldg(en_offset + k);
                    c += o * o;
                }
            }
        } else if (t >= ITEM_SEG && t < TAIL_THREADS) {
            int r = t - ITEM_SEG;
            int b = r >> 4, lane = r & 15;
            float4 u = __ldg((const float4*)user_emb + (size_t)__ldg(user_ids + b) * 16 + lane);
            c = sumsq4(u);
        }
#pragma unroll
        for (int s = 1; s <= 16; s <<= 1) c += __shfl_xor_sync(0xffffffffu, c, s);
        if ((threadIdx.x & 31) == 0 && c != 0.0f) atomicAdd(&bacc, c);
        __syncthreads();
        if (threadIdx.x == 0 && bacc != 0.0f && reg_out) atomicAdd(reg_out, 0.5f * bacc);
    }
}

// ---------------- launch ----------------
static void launch_pdl(void* fn, dim3 grid, void** args) {
    cudaLaunchConfig_t cfg = {};
    cfg.gridDim = grid;
    cfg.blockDim = dim3(256);
    cfg.dynamicSmemBytes = 0;
    cfg.stream = 0;
    cudaLaunchAttribute attr[1];
    attr[0].id = cudaLaunchAttributeProgrammaticStreamSerialization;
    attr[0].val.programmaticStreamSerializationAllowed = 1;
    cfg.attrs = attr;
    cfg.numAttrs = 1;
    cudaLaunchKernelExC(&cfg, fn, args);
}

extern "C" void kernel_launch(void* const* d_in, const int* in_sizes, int n_in,
                              void* d_out, int out_size) {
    const int*   user_ids  = (const int*)d_in[0];
    const int*   bat_idx   = (const int*)d_in[1];
    const int*   sp_row    = (const int*)d_in[2];
    const int*   sp_col    = (const int*)d_in[3];
    const int*   bat_items = (const int*)d_in[4];
    const float* en_emb    = (const float*)d_in[5];
    const float* en_offset = (const float*)d_in[6];
    const float* de_emb    = (const float*)d_in[7];
    const float* de_bias   = (const float*)d_in[8];
    const float* user_emb  = (const float*)d_in[9];
    float* out = (float*)d_out;
    float* reg_out = (out_size > N_PAIRS) ? (out + N_PAIRS) : nullptr;

    // K1: de/en streaming pass (normal launch)
    k_pre<<<PRE_BLOCKS, 256>>>(de_emb, en_emb, de_bias, reg_out);
    // K2: bin + mask — PDL, no internal sync: overlaps K1 (disjoint buffers)
    {
        void* args[] = { (void*)&sp_row, (void*)&sp_col, (void*)&bat_items };
        launch_pdl((void*)k_bin, dim3(BIN_BLOCKS), args);
    }
    // K3: row gather + tanh + fp16 (PDL + sync)
    {
        void* args[] = { (void*)&user_ids, (void*)&user_emb, (void*)&en_offset,
                         (void*)&en_emb };
        launch_pdl((void*)k_row, dim3(ROW_BLOCKS), args);
    }
    // K4: decode + reg tail (PDL + sync)
    {
        void* args[] = { (void*)&bat_idx, (void*)&bat_items, (void*)&de_bias,
                         (void*)&en_offset, (void*)&user_emb, (void*)&user_ids,
                         (void*)&out, (void*)&reg_out };
        launch_pdl((void*)k_decode_reg, dim3(DECODE_BLOCKS + TAIL_BLOCKS), args);
    }
}

// round 17
// speedup vs baseline: 1.0764x; 1.0764x over previous
#include <cuda_runtime.h>
#include <cuda_fp16.h>
#include <stdint.h>

#define B_USERS     4096
#define D_DIM       64
#define NNZ_CNT     204800
#define N_PAIRS     1048576
#define NUM_ITEMS_C 100000

#define DECODE_BLOCKS (N_PAIRS * 2 / 256)            // 8192 (4 pairs per 8-lane group)
#define ITEM_SEG      100352                          // items segment, padded to /256
#define USER_SEG      (B_USERS * 16)                  // 65536
#define TAIL_THREADS  (ITEM_SEG + USER_SEG)           // 165888
#define TAIL_BLOCKS   (TAIL_THREADS / 256)            // 648
#define PRE_THREADS   (NUM_ITEMS_C * D_DIM / 8)       // 800000 (8 threads/row, exact /256)

// Scratch (no cudaMalloc allowed)
__device__ float         g_hidden[B_USERS * D_DIM];
__device__ __half        g_hidden_h[B_USERS * D_DIM];
__device__ __half        g_de_h[NUM_ITEMS_C * D_DIM];
__device__ float         g_item_reg[NUM_ITEMS_C];
__device__ unsigned char g_mask[NUM_ITEMS_C];

// ---------------- Threefry-2x32 (JAX partitionable path) ----------------
__device__ __forceinline__ uint32_t rotl32(uint32_t x, int r) {
    return (x << r) | (x >> (32 - r));
}

__device__ __forceinline__ uint32_t threefry_bits(uint32_t ctr_lo) {
    const uint32_t ks0 = 0u, ks1 = 42u;
    const uint32_t ks2 = ks0 ^ ks1 ^ 0x1BD11BDAu;
    uint32_t x0 = 0u  + ks0;
    uint32_t x1 = ctr_lo + ks1;

    x0 += x1; x1 = rotl32(x1, 13); x1 ^= x0;
    x0 += x1; x1 = rotl32(x1, 15); x1 ^= x0;
    x0 += x1; x1 = rotl32(x1, 26); x1 ^= x0;
    x0 += x1; x1 = rotl32(x1,  6); x1 ^= x0;
    x0 += ks1; x1 += ks2 + 1u;
    x0 += x1; x1 = rotl32(x1, 17); x1 ^= x0;
    x0 += x1; x1 = rotl32(x1, 29); x1 ^= x0;
    x0 += x1; x1 = rotl32(x1, 16); x1 ^= x0;
    x0 += x1; x1 = rotl32(x1, 24); x1 ^= x0;
    x0 += ks2; x1 += ks0 + 2u;
    x0 += x1; x1 = rotl32(x1, 13); x1 ^= x0;
    x0 += x1; x1 = rotl32(x1, 15); x1 ^= x0;
    x0 += x1; x1 = rotl32(x1, 26); x1 ^= x0;
    x0 += x1; x1 = rotl32(x1,  6); x1 ^= x0;
    x0 += ks0; x1 += ks1 + 3u;
    x0 += x1; x1 = rotl32(x1, 17); x1 ^= x0;
    x0 += x1; x1 = rotl32(x1, 29); x1 ^= x0;
    x0 += x1; x1 = rotl32(x1, 16); x1 ^= x0;
    x0 += x1; x1 = rotl32(x1, 24); x1 ^= x0;
    x0 += ks1; x1 += ks2 + 4u;
    x0 += x1; x1 = rotl32(x1, 13); x1 ^= x0;
    x0 += x1; x1 = rotl32(x1, 15); x1 ^= x0;
    x0 += x1; x1 = rotl32(x1, 26); x1 ^= x0;
    x0 += x1; x1 = rotl32(x1,  6); x1 ^= x0;
    x0 += ks2; x1 += ks0 + 5u;

    return x0 ^ x1;
}

// ---------------- fp16 pack helpers ----------------
__device__ __forceinline__ uint32_t pack_h2(float a, float b) {
    __half2 h = __floats2half2_rn(a, b);
    return *reinterpret_cast<uint32_t*>(&h);
}
__device__ __forceinline__ uint4 pack_8(float4 a, float4 b) {
    return make_uint4(pack_h2(a.x, a.y), pack_h2(a.z, a.w),
                      pack_h2(b.x, b.y), pack_h2(b.z, b.w));
}
__device__ __forceinline__ float sumsq4(float4 v) {
    return v.x * v.x + v.y * v.y + v.z * v.z + v.w * v.w;
}

// ---------------- K1: fused preamble (R8-exact) ----------------
// de convert -> fp16 | item reg norms (en+de+bias) | hidden init | zero mask/reg
__global__ void k_pre(const float* __restrict__ de_emb,
                      const float* __restrict__ en_emb,
                      const float* __restrict__ de_bias,
                      const int*   __restrict__ user_ids,
                      const float* __restrict__ user_emb,
                      const float* __restrict__ en_offset,
                      float* reg_out) {
    int idx = blockIdx.x * blockDim.x + threadIdx.x;   // exact: PRE_THREADS
    int row  = idx >> 3;      // 8 threads per item row
    int l8   = idx & 7;

    float4 a = __ldg((const float4*)de_emb + idx * 2);
    float4 b = __ldg((const float4*)de_emb + idx * 2 + 1);
    ((uint4*)g_de_h)[idx] = pack_8(a, b);
    float c = sumsq4(a) + sumsq4(b);

    float4 ea = __ldg((const float4*)en_emb + idx * 2);
    float4 eb = __ldg((const float4*)en_emb + idx * 2 + 1);
    c += sumsq4(ea) + sumsq4(eb);

    c += __shfl_xor_sync(0xffffffffu, c, 1);
    c += __shfl_xor_sync(0xffffffffu, c, 2);
    c += __shfl_xor_sync(0xffffffffu, c, 4);
    if (l8 == 0) {
        float bb = __ldg(de_bias + row);
        g_item_reg[row] = c + bb * bb;
    }

    if (idx < B_USERS * D_DIM / 4) {
        int bu = idx >> 4;
        int d4 = idx & 15;
        float4 u = __ldg((const float4*)user_emb + (size_t)__ldg(user_ids + bu) * 16 + d4);
        float4 o = __ldg((const float4*)en_offset + d4);
        ((float4*)g_hidden)[idx] = make_float4(u.x + o.x, u.y + o.y, u.z + o.z, u.w + o.w);
    }
    if (idx * 4 < NUM_ITEMS_C) ((uint32_t*)g_mask)[idx] = 0;
    if (idx == 0 && reg_out) *reg_out = 0.0f;
}

// ---------------- K2: scatter + item-mask (R8-exact) ----------------
__global__ void k_scatter(const int* __restrict__ sp_row,
                          const int* __restrict__ sp_col,
                          const float* __restrict__ en_emb,
                          const int* __restrict__ bat_items) {
    int t    = blockIdx.x * blockDim.x + threadIdx.x;
    int i    = t >> 4;
    int lane = t & 15;
    int wl   = threadIdx.x & 31;

    uint32_t keep = 0;
    if (lane == 0) {
        uint32_t bits = threefry_bits((uint32_t)i);
        float u = __uint_as_float((bits >> 9) | 0x3f800000u) - 1.0f;
        keep = (u < 0.8f) ? 1u : 0u;
    }
    keep = __shfl_sync(0xffffffffu, keep, wl & 16, 32);
    int item = (t < N_PAIRS) ? __ldg(bat_items + t) : -1;

    cudaGridDependencySynchronize();   // K1 complete

    if (item >= 0) g_mask[item] = 1;
    if (!keep) return;

    int row = __ldg(sp_row + i);
    int col = __ldg(sp_col + i);
    float4 e = __ldg((const float4*)en_emb + (size_t)col * 16 + lane);
    float4 v = make_float4(1.25f * e.x, 1.25f * e.y, 1.25f * e.z, 1.25f * e.w);
    atomicAdd((float4*)(g_hidden + (size_t)row * 64 + lane * 4), v);
}

// ---------------- K3: tanh + fp16 copy — 4 elems/thread, 512 blocks ----------------
__global__ void k_tanh() {
    cudaGridDependencySynchronize();
    int idx = blockIdx.x * blockDim.x + threadIdx.x;   // exact: B*D/4 = 65536
    float4 a = ((const float4*)g_hidden)[idx];
    a = make_float4(tanhf(a.x), tanhf(a.y), tanhf(a.z), tanhf(a.w));
    uint2 p = make_uint2(pack_h2(a.x, a.y), pack_h2(a.z, a.w));
    ((uint2*)g_hidden_h)[idx] = p;
}

// ---------------- K4: decode + tiny reg tail (R8-exact) ----------------
__device__ __forceinline__ float dot8h(uint4 hv, uint4 ev) {
    float acc = 0.0f;
    const uint32_t* hw = (const uint32_t*)&hv;
    const uint32_t* ew = (const uint32_t*)&ev;
#pragma unroll
    for (int i = 0; i < 4; i++) {
        float2 f = __half22float2(*(const __half2*)&hw[i]);
        float2 g = __half22float2(*(const __half2*)&ew[i]);
        acc += f.x * g.x + f.y * g.y;
    }
    return acc;
}

__global__ void __launch_bounds__(256) k_decode_reg(
        const int* __restrict__ bat_idx,
        const int* __restrict__ bat_items,
        const float* __restrict__ de_bias,
        const float* __restrict__ en_offset,
        const float* __restrict__ user_emb,
        const int*   __restrict__ user_ids,
        float* __restrict__ out,
        float* __restrict__ reg_out) {
    if (blockIdx.x < DECODE_BLOCKS) {
        int t = blockIdx.x * blockDim.x + threadIdx.x;
        int g = t >> 3;             // group handles pairs 4g..4g+3
        int l = t & 7;

        int4 bb = __ldg((const int4*)bat_idx + g);
        int4 ii = __ldg((const int4*)bat_items + g);
        cudaGridDependencySynchronize();   // hidden_h ready

        uint4 h0 = ((const uint4*)g_hidden_h + (size_t)bb.x * 8)[l];
        uint4 h1 = ((const uint4*)g_hidden_h + (size_t)bb.y * 8)[l];
        uint4 h2 = ((const uint4*)g_hidden_h + (size_t)bb.z * 8)[l];
        uint4 h3 = ((const uint4*)g_hidden_h + (size_t)bb.w * 8)[l];
        uint4 e0 = ((const uint4*)g_de_h + (size_t)ii.x * 8)[l];
        uint4 e1 = ((const uint4*)g_de_h + (size_t)ii.y * 8)[l];
        uint4 e2 = ((const uint4*)g_de_h + (size_t)ii.z * 8)[l];
        uint4 e3 = ((const uint4*)g_de_h + (size_t)ii.w * 8)[l];

        float p0 = dot8h(h0, e0);
        float p1 = dot8h(h1, e1);
        float p2 = dot8h(h2, e2);
        float p3 = dot8h(h3, e3);
#pragma unroll
        for (int s = 1; s <= 4; s <<= 1) {
            p0 += __shfl_xor_sync(0xffffffffu, p0, s);
            p1 += __shfl_xor_sync(0xffffffffu, p1, s);
            p2 += __shfl_xor_sync(0xffffffffu, p2, s);
            p3 += __shfl_xor_sync(0xffffffffu, p3, s);
        }
        if (l == 0) {
            float4 r = make_float4(p0 + __ldg(de_bias + ii.x),
                                   p1 + __ldg(de_bias + ii.y),
                                   p2 + __ldg(de_bias + ii.z),
                                   p3 + __ldg(de_bias + ii.w));
            ((float4*)out)[g] = r;
        }
    } else {
        cudaGridDependencySynchronize();   // g_mask (K2), g_item_reg (K1)
        __shared__ float bacc;
        if (threadIdx.x == 0) bacc = 0.0f;
        __syncthreads();

        int t = (blockIdx.x - DECODE_BLOCKS) * blockDim.x + threadIdx.x;
        float c = 0.0f;
        if (t < NUM_ITEMS_C) {
            c = g_mask[t] ? g_item_reg[t] : 0.0f;
            if (t == 0) {
                for (int k = 0; k < D_DIM; k++) {
                    float o = __ldg(en_offset + k);
                    c += o * o;
                }
            }
        } else if (t >= ITEM_SEG && t < TAIL_THREADS) {
            int r = t - ITEM_SEG;
            int b = r >> 4, lane = r & 15;
            float4 u = __ldg((const float4*)user_emb + (size_t)__ldg(user_ids + b) * 16 + lane);
            c = sumsq4(u);
        }
#pragma unroll
        for (int s = 1; s <= 16; s <<= 1) c += __shfl_xor_sync(0xffffffffu, c, s);
        if ((threadIdx.x & 31) == 0 && c != 0.0f) atomicAdd(&bacc, c);
        __syncthreads();
        if (threadIdx.x == 0 && bacc != 0.0f && reg_out) atomicAdd(reg_out, 0.5f * bacc);
    }
}

// ---------------- launch ----------------
static void launch_pdl(void* fn, dim3 grid, void** args) {
    cudaLaunchConfig_t cfg = {};
    cfg.gridDim = grid;
    cfg.blockDim = dim3(256);
    cfg.dynamicSmemBytes = 0;
    cfg.stream = 0;
    cudaLaunchAttribute attr[1];
    attr[0].id = cudaLaunchAttributeProgrammaticStreamSerialization;
    attr[0].val.programmaticStreamSerializationAllowed = 1;
    cfg.attrs = attr;
    cfg.numAttrs = 1;
    cudaLaunchKernelExC(&cfg, fn, args);
}

extern "C" void kernel_launch(void* const* d_in, const int* in_sizes, int n_in,
                              void* d_out, int out_size) {
    const int*   user_ids  = (const int*)d_in[0];
    const int*   bat_idx   = (const int*)d_in[1];
    const int*   sp_row    = (const int*)d_in[2];
    const int*   sp_col    = (const int*)d_in[3];
    const int*   bat_items = (const int*)d_in[4];
    const float* en_emb    = (const float*)d_in[5];
    const float* en_offset = (const float*)d_in[6];
    const float* de_emb    = (const float*)d_in[7];
    const float* de_bias   = (const float*)d_in[8];
    const float* user_emb  = (const float*)d_in[9];
    float* out = (float*)d_out;
    float* reg_out = (out_size > N_PAIRS) ? (out + N_PAIRS) : nullptr;

    k_pre<<<PRE_THREADS / 256, 256>>>(de_emb, en_emb, de_bias, user_ids,
                                      user_emb, en_offset, reg_out);
    {
        void* args[] = { (void*)&sp_row, (void*)&sp_col, (void*)&en_emb, (void*)&bat_items };
        launch_pdl((void*)k_scatter, dim3(NNZ_CNT * 16 / 256), args);
    }
    {
        void* args[] = {};
        launch_pdl((void*)k_tanh, dim3(B_USERS * D_DIM / 4 / 256), args);
    }
    {
        void* args[] = { (void*)&bat_idx, (void*)&bat_items, (void*)&de_bias,
                         (void*)&en_offset, (void*)&user_emb, (void*)&user_ids,
                         (void*)&out, (void*)&reg_out };
        launch_pdl((void*)k_decode_reg, dim3(DECODE_BLOCKS + TAIL_BLOCKS), args);
    }
}